// round 1
// baseline (speedup 1.0000x reference)
#include <cuda_runtime.h>
#include <math.h>

// Problem constants: B=4, S=2048, D=2048, H=16, Dh=128
#define BB 4
#define SS 2048
#define DD 2048
#define HH 16
#define DH 128
#define TT 8192            // B*S tokens

// ---------------- scratch (static device arrays; no allocation allowed) ----
__device__ float g_Xn [8192ULL * 2048];          //  64 MB   layernorm output
__device__ float g_QKV[8192ULL * 6144];          // 192 MB   [token, 3D]  Q|K|V
__device__ float g_ctx[8192ULL * 2048];          //  64 MB   attention context
__device__ float g_sc [64ULL * 2048 * 2048];     //   1 GB   scores/probs per (b,h)

// ---------------------------------------------------------------- layernorm
__global__ void ln_kernel(const float* __restrict__ X,
                          const float* __restrict__ w,
                          const float* __restrict__ b,
                          float* __restrict__ Y) {
    const int D = 2048;
    const float* x = X + (size_t)blockIdx.x * D;
    float* y       = Y + (size_t)blockIdx.x * D;
    int tid = threadIdx.x;

    float v[8];
    float s = 0.f;
#pragma unroll
    for (int i = 0; i < 8; i++) { v[i] = x[tid + i * 256]; s += v[i]; }

    __shared__ float sh[8];
#pragma unroll
    for (int o = 16; o > 0; o >>= 1) s += __shfl_xor_sync(0xffffffffu, s, o);
    if ((tid & 31) == 0) sh[tid >> 5] = s;
    __syncthreads();
    float tot = 0.f;
#pragma unroll
    for (int i = 0; i < 8; i++) tot += sh[i];
    float mean = tot * (1.0f / 2048.0f);

    float sq = 0.f;
#pragma unroll
    for (int i = 0; i < 8; i++) { float d = v[i] - mean; sq += d * d; }
    __syncthreads();
#pragma unroll
    for (int o = 16; o > 0; o >>= 1) sq += __shfl_xor_sync(0xffffffffu, sq, o);
    if ((tid & 31) == 0) sh[tid >> 5] = sq;
    __syncthreads();
    float vtot = 0.f;
#pragma unroll
    for (int i = 0; i < 8; i++) vtot += sh[i];
    float rstd = rsqrtf(vtot * (1.0f / 2048.0f) + 1e-5f);

#pragma unroll
    for (int i = 0; i < 8; i++) {
        int c = tid + i * 256;
        y[c] = (v[i] - mean) * rstd * w[c] + b[c];
    }
}

// --------------------------------------------------------------------- rope
// Interleaved RoPE on first Dh/2 = 64 channels; channels 64..127 untouched.
// One thread per (token, head, pair j<32); handles both Q and K.
__global__ void rope_kernel(float* __restrict__ QKV) {
    int idx = blockIdx.x * blockDim.x + threadIdx.x;   // 8192*16*32 total
    if (idx >= 8192 * 16 * 32) return;
    int j = idx & 31;
    int h = (idx >> 5) & 15;
    int t = idx >> 9;
    int s = t & 2047;                                  // position within sequence

    // inv_freq[j] = 10000^(-j/32); compute in double, round to fp32 (match jnp fp32)
    float inv = (float)exp(-(double)j * (9.210340371976184 / 32.0));
    float ang = (float)s * inv;
    float c, si;
    __sincosf(ang, &si, &c);
    // use precise sin/cos for large args
    si = sinf(ang); c = cosf(ang);

    size_t base = (size_t)t * 6144 + (size_t)h * 128 + 2 * j;
    float* q = QKV + base;
    float* k = QKV + base + 2048;
    float q0 = q[0], q1 = q[1];
    q[0] = q0 * c - q1 * si;
    q[1] = q1 * c + q0 * si;
    float k0 = k[0], k1 = k[1];
    k[0] = k0 * c - k1 * si;
    k[1] = k1 * c + k0 * si;
}

// ------------------------------------------------------------------ softmax
__global__ void softmax_kernel(float* __restrict__ S) {
    const int N = 2048;
    float* row = S + (size_t)blockIdx.x * N;
    int tid = threadIdx.x;

    float v[8];
    float m = -1e30f;
#pragma unroll
    for (int i = 0; i < 8; i++) { v[i] = row[tid + i * 256]; m = fmaxf(m, v[i]); }

    __shared__ float sh[8];
#pragma unroll
    for (int o = 16; o > 0; o >>= 1) m = fmaxf(m, __shfl_xor_sync(0xffffffffu, m, o));
    if ((tid & 31) == 0) sh[tid >> 5] = m;
    __syncthreads();
    float rm = -1e30f;
#pragma unroll
    for (int i = 0; i < 8; i++) rm = fmaxf(rm, sh[i]);

    float s = 0.f;
#pragma unroll
    for (int i = 0; i < 8; i++) { v[i] = __expf(v[i] - rm); s += v[i]; }
    __syncthreads();
#pragma unroll
    for (int o = 16; o > 0; o >>= 1) s += __shfl_xor_sync(0xffffffffu, s, o);
    if ((tid & 31) == 0) sh[tid >> 5] = s;
    __syncthreads();
    float tot = 0.f;
#pragma unroll
    for (int i = 0; i < 8; i++) tot += sh[i];
    float inv = 1.0f / tot;

#pragma unroll
    for (int i = 0; i < 8; i++) row[tid + i * 256] = v[i] * inv;
}

// --------------------------------------------------------------------- gemm
// C[M,N] = alpha * A[M,K] @ op(B) (+ residual), batched over z = b*Hs + h.
// TRANSB=false: B row-major [K,N]; TRANSB=true: B row-major [N,K] (C = A B^T).
// Tile 128x128x16, 256 threads, 8x8 per-thread microtile.
template <bool TRANSB>
__global__ void __launch_bounds__(256, 2)
gemm_kernel(const float* __restrict__ A, const float* __restrict__ B,
            float* __restrict__ C, const float* __restrict__ Res,
            int M, int N, int K, int lda, int ldb, int ldc,
            long long aB, long long aH, long long bB, long long bH,
            long long cB, long long cH, int Hs, float alpha) {
    int z = blockIdx.z;
    int bb = z / Hs, hh = z % Hs;
    A += bb * aB + hh * aH;
    B += bb * bB + hh * bH;
    C += bb * cB + hh * cH;
    if (Res) Res += bb * cB + hh * cH;

    __shared__ float As[16][128];
    __shared__ float Bs[16][128];

    int tid  = threadIdx.x;
    int row0 = blockIdx.y * 128;
    int col0 = blockIdx.x * 128;
    int tx = tid & 15, ty = tid >> 4;

    float acc[8][8];
#pragma unroll
    for (int i = 0; i < 8; i++)
#pragma unroll
        for (int j = 0; j < 8; j++) acc[i][j] = 0.f;

    for (int k0 = 0; k0 < K; k0 += 16) {
        // load A tile 128x16 -> As[k][m]
#pragma unroll
        for (int it = 0; it < 2; it++) {
            int idx4 = tid + it * 256;            // 0..511
            int m  = idx4 >> 2;
            int k4 = (idx4 & 3) << 2;
            float4 va = *(const float4*)&A[(long long)(row0 + m) * lda + k0 + k4];
            As[k4 + 0][m] = va.x; As[k4 + 1][m] = va.y;
            As[k4 + 2][m] = va.z; As[k4 + 3][m] = va.w;
        }
        // load B tile -> Bs[k][n]
        if (!TRANSB) {
#pragma unroll
            for (int it = 0; it < 2; it++) {
                int idx4 = tid + it * 256;
                int kk = idx4 >> 5;
                int n4 = (idx4 & 31) << 2;
                float4 vb = *(const float4*)&B[(long long)(k0 + kk) * ldb + col0 + n4];
                *(float4*)&Bs[kk][n4] = vb;
            }
        } else {
#pragma unroll
            for (int it = 0; it < 2; it++) {
                int idx4 = tid + it * 256;
                int n  = idx4 >> 2;
                int k4 = (idx4 & 3) << 2;
                float4 vb = *(const float4*)&B[(long long)(col0 + n) * ldb + k0 + k4];
                Bs[k4 + 0][n] = vb.x; Bs[k4 + 1][n] = vb.y;
                Bs[k4 + 2][n] = vb.z; Bs[k4 + 3][n] = vb.w;
            }
        }
        __syncthreads();

#pragma unroll
        for (int k = 0; k < 16; k++) {
            float a[8], b[8];
            *(float4*)&a[0] = *(const float4*)&As[k][ty * 8];
            *(float4*)&a[4] = *(const float4*)&As[k][ty * 8 + 4];
            *(float4*)&b[0] = *(const float4*)&Bs[k][tx * 8];
            *(float4*)&b[4] = *(const float4*)&Bs[k][tx * 8 + 4];
#pragma unroll
            for (int i = 0; i < 8; i++)
#pragma unroll
                for (int j = 0; j < 8; j++) acc[i][j] += a[i] * b[j];
        }
        __syncthreads();
    }

    // epilogue
#pragma unroll
    for (int i = 0; i < 8; i++) {
        long long r = row0 + ty * 8 + i;
#pragma unroll
        for (int j = 0; j < 8; j += 4) {
            long long c = col0 + tx * 8 + j;
            float4 o;
            o.x = acc[i][j + 0] * alpha;
            o.y = acc[i][j + 1] * alpha;
            o.z = acc[i][j + 2] * alpha;
            o.w = acc[i][j + 3] * alpha;
            if (Res) {
                const float4 rv = *(const float4*)&Res[r * ldc + c];
                o.x += rv.x; o.y += rv.y; o.z += rv.z; o.w += rv.w;
            }
            *(float4*)&C[r * ldc + c] = o;
        }
    }
}

// ------------------------------------------------------------------- launch
extern "C" void kernel_launch(void* const* d_in, const int* in_sizes, int n_in,
                              void* d_out, int out_size) {
    const float* X    = (const float*)d_in[0];
    const float* ln_w = (const float*)d_in[1];
    const float* ln_b = (const float*)d_in[2];
    const float* W_in = (const float*)d_in[3];
    const float* W_out= (const float*)d_in[4];
    float* out = (float*)d_out;

    float *Xn, *QKV, *CTX, *SC;
    cudaGetSymbolAddress((void**)&Xn,  g_Xn);
    cudaGetSymbolAddress((void**)&QKV, g_QKV);
    cudaGetSymbolAddress((void**)&CTX, g_ctx);
    cudaGetSymbolAddress((void**)&SC,  g_sc);

    // 1) layernorm: X[8192,2048] -> Xn
    ln_kernel<<<TT, 256>>>(X, ln_w, ln_b, Xn);

    // 2) QKV = Xn @ W_in   [8192,6144]
    gemm_kernel<false><<<dim3(6144 / 128, 8192 / 128, 1), 256>>>(
        Xn, W_in, QKV, nullptr,
        8192, 6144, 2048, 2048, 6144, 6144,
        0, 0, 0, 0, 0, 0, 1, 1.0f);

    // 3) RoPE on Q and K (in place)
    rope_kernel<<<(8192 * 16 * 32) / 256, 256>>>(QKV);

    // 4) scores(b,h) = (1/sqrt(128)) * Q @ K^T   [64][2048,2048]
    const float scale = 0.08838834764831845f;  // 1/sqrt(128)
    gemm_kernel<true><<<dim3(16, 16, 64), 256>>>(
        QKV /*Q*/, QKV + 2048 /*K*/, SC, nullptr,
        2048, 2048, 128, 6144, 6144, 2048,
        2048LL * 6144, 128,            // A: b,h strides
        2048LL * 6144, 128,            // B: b,h strides
        16LL * 2048 * 2048, 2048LL * 2048,  // C: b,h strides
        HH, scale);

    // 5) softmax rows (in place)
    softmax_kernel<<<64 * 2048, 256>>>(SC);

    // 6) ctx(b,h) = probs @ V   -> g_ctx laid out [token, D]
    gemm_kernel<false><<<dim3(1, 16, 64), 256>>>(
        SC, QKV + 4096, CTX, nullptr,
        2048, 128, 2048, 2048, 6144, 2048,
        16LL * 2048 * 2048, 2048LL * 2048,
        2048LL * 6144, 128,
        2048LL * 2048, 128,
        HH, 1.0f);

    // 7) out = ctx @ W_out + X   [8192,2048]
    gemm_kernel<false><<<dim3(2048 / 128, 8192 / 128, 1), 256>>>(
        CTX, W_out, out, X,
        8192, 2048, 2048, 2048, 2048, 2048,
        0, 0, 0, 0, 0, 0, 1, 1.0f);
}

// round 2
// speedup vs baseline: 1.4734x; 1.4734x over previous
#include <cuda_runtime.h>
#include <math.h>

// Problem constants: B=4, S=2048, D=2048, H=16, Dh=128
#define TT 8192            // B*S tokens

// ---------------- scratch (static device arrays; no allocation allowed) ----
__device__ float g_Xn [8192ULL * 2048];          //  64 MB   layernorm output
__device__ float g_QKV[8192ULL * 6144];          // 192 MB   [token, 3D]  Q|K|V
__device__ float g_ctx[8192ULL * 2048];          //  64 MB   attention context
__device__ float g_sc [64ULL * 2048 * 2048];     //   1 GB   scores/probs per (b,h)

// ---------------------------------------------------------------- layernorm
__global__ void ln_kernel(const float* __restrict__ X,
                          const float* __restrict__ w,
                          const float* __restrict__ b,
                          float* __restrict__ Y) {
    const int D = 2048;
    const float* x = X + (size_t)blockIdx.x * D;
    float* y       = Y + (size_t)blockIdx.x * D;
    int tid = threadIdx.x;

    float v[8];
    float s = 0.f;
#pragma unroll
    for (int i = 0; i < 8; i++) { v[i] = x[tid + i * 256]; s += v[i]; }

    __shared__ float sh[8];
#pragma unroll
    for (int o = 16; o > 0; o >>= 1) s += __shfl_xor_sync(0xffffffffu, s, o);
    if ((tid & 31) == 0) sh[tid >> 5] = s;
    __syncthreads();
    float tot = 0.f;
#pragma unroll
    for (int i = 0; i < 8; i++) tot += sh[i];
    float mean = tot * (1.0f / 2048.0f);

    float sq = 0.f;
#pragma unroll
    for (int i = 0; i < 8; i++) { float d = v[i] - mean; sq += d * d; }
    __syncthreads();
#pragma unroll
    for (int o = 16; o > 0; o >>= 1) sq += __shfl_xor_sync(0xffffffffu, sq, o);
    if ((tid & 31) == 0) sh[tid >> 5] = sq;
    __syncthreads();
    float vtot = 0.f;
#pragma unroll
    for (int i = 0; i < 8; i++) vtot += sh[i];
    float rstd = rsqrtf(vtot * (1.0f / 2048.0f) + 1e-5f);

#pragma unroll
    for (int i = 0; i < 8; i++) {
        int c = tid + i * 256;
        y[c] = (v[i] - mean) * rstd * w[c] + b[c];
    }
}

// --------------------------------------------------------------------- rope
__global__ void rope_kernel(float* __restrict__ QKV) {
    int idx = blockIdx.x * blockDim.x + threadIdx.x;   // 8192*16*32 total
    if (idx >= 8192 * 16 * 32) return;
    int j = idx & 31;
    int h = (idx >> 5) & 15;
    int t = idx >> 9;
    int s = t & 2047;

    float inv = (float)exp(-(double)j * (9.210340371976184 / 32.0));
    float ang = (float)s * inv;
    float si = sinf(ang), c = cosf(ang);

    size_t base = (size_t)t * 6144 + (size_t)h * 128 + 2 * j;
    float* q = QKV + base;
    float* k = QKV + base + 2048;
    float q0 = q[0], q1 = q[1];
    q[0] = q0 * c - q1 * si;
    q[1] = q1 * c + q0 * si;
    float k0 = k[0], k1 = k[1];
    k[0] = k0 * c - k1 * si;
    k[1] = k1 * c + k0 * si;
}

// ------------------------------------------------------------------ softmax
__global__ void softmax_kernel(float* __restrict__ S) {
    const int N = 2048;
    float* row = S + (size_t)blockIdx.x * N;
    int tid = threadIdx.x;

    float v[8];
    float m = -1e30f;
#pragma unroll
    for (int i = 0; i < 8; i++) { v[i] = row[tid + i * 256]; m = fmaxf(m, v[i]); }

    __shared__ float sh[8];
#pragma unroll
    for (int o = 16; o > 0; o >>= 1) m = fmaxf(m, __shfl_xor_sync(0xffffffffu, m, o));
    if ((tid & 31) == 0) sh[tid >> 5] = m;
    __syncthreads();
    float rm = -1e30f;
#pragma unroll
    for (int i = 0; i < 8; i++) rm = fmaxf(rm, sh[i]);

    float s = 0.f;
#pragma unroll
    for (int i = 0; i < 8; i++) { v[i] = __expf(v[i] - rm); s += v[i]; }
    __syncthreads();
#pragma unroll
    for (int o = 16; o > 0; o >>= 1) s += __shfl_xor_sync(0xffffffffu, s, o);
    if ((tid & 31) == 0) sh[tid >> 5] = s;
    __syncthreads();
    float tot = 0.f;
#pragma unroll
    for (int i = 0; i < 8; i++) tot += sh[i];
    float inv = 1.0f / tot;

#pragma unroll
    for (int i = 0; i < 8; i++) row[tid + i * 256] = v[i] * inv;
}

// ---------------------------------------------------------------- tf32 gemm
__device__ __forceinline__ unsigned f2tf(float x) {
    unsigned u;
    asm("cvt.rna.tf32.f32 %0, %1;" : "=r"(u) : "f"(x));
    return u;
}

#define MMA8(c, a0, a1, a2, a3, b0, b1)                                      \
    asm volatile(                                                            \
        "mma.sync.aligned.m16n8k8.row.col.f32.tf32.tf32.f32 "                \
        "{%0,%1,%2,%3}, {%4,%5,%6,%7}, {%8,%9}, {%0,%1,%2,%3};"              \
        : "+f"(c[0]), "+f"(c[1]), "+f"(c[2]), "+f"(c[3])                     \
        : "r"(a0), "r"(a1), "r"(a2), "r"(a3), "r"(b0), "r"(b1))

// C[M,N] = alpha * A[M,K] @ op(B) (+Res), batched over z = b*Hs + h.
// TRANSB=false: B is [K,N]; TRANSB=true: B is [N,K] (C = A B^T).
// Block tile 128x128x32, 256 threads (8 warps 2x4), warp tile 64x32.
// Smem inner-k within each 8-chunk permuted (0,4,1,5,2,6,3,7) so that the
// (c, c+4) fragment pair is one LDS.64.
template <bool TRANSB>
__global__ void __launch_bounds__(256)
gemm_tf32(const float* __restrict__ A, const float* __restrict__ B,
          float* __restrict__ C, const float* __restrict__ Res,
          int M, int N, int K, int lda, int ldb, int ldc,
          long long aB, long long aH, long long bB, long long bH,
          long long cB, long long cH, int Hs, float alpha) {
    int z = blockIdx.z;
    int bb = z / Hs, hh = z % Hs;
    A += bb * aB + hh * aH;
    B += bb * bB + hh * bH;
    C += bb * cB + hh * cH;
    const float* R = Res ? Res + bb * cB + hh * cH : nullptr;

    __shared__ float As[128][36];
    __shared__ float Bs[128][36];

    const int tid  = threadIdx.x;
    const int row0 = blockIdx.y * 128;
    const int col0 = blockIdx.x * 128;
    const int warp = tid >> 5, lane = tid & 31;
    const int wm = warp & 1, wn = warp >> 1;      // 2 x 4 warps
    const int mbase = wm * 64, nbase = wn * 32;   // warp tile 64x32
    const int gid = lane >> 2, tig = lane & 3;

    float acc[4][4][4];
#pragma unroll
    for (int i = 0; i < 4; i++)
#pragma unroll
        for (int j = 0; j < 4; j++)
#pragma unroll
            for (int l = 0; l < 4; l++) acc[i][j][l] = 0.f;

    // per-thread gmem tile coords
    // A: idx = tid + i*256 -> m = idx>>3, k4 = (idx&7)*4
    const int a_m  = tid >> 3;            // rows stride 32 per i (256/8)
    const int a_k4 = (tid & 7) << 2;
    // B (!TRANSB): k = idx>>5, n4 = (idx&31)*4
    const int b_k  = tid >> 5;            // +8 per i
    const int b_n4 = (tid & 31) << 2;

    float4 ra[4], rb[4];

    auto load_tiles = [&](int k0) {
#pragma unroll
        for (int i = 0; i < 4; i++) {
            int m = a_m + i * 32;
            ra[i] = *(const float4*)&A[(long long)(row0 + m) * lda + k0 + a_k4];
        }
        if (!TRANSB) {
#pragma unroll
            for (int i = 0; i < 4; i++) {
                int k = b_k + i * 8;
                rb[i] = *(const float4*)&B[(long long)(k0 + k) * ldb + col0 + b_n4];
            }
        } else {
#pragma unroll
            for (int i = 0; i < 4; i++) {
                int n = a_m + i * 32;
                rb[i] = *(const float4*)&B[(long long)(col0 + n) * ldb + k0 + a_k4];
            }
        }
    };

    auto store_tiles = [&]() {
        // A: k4..k4+3 map to chunk*8 + base + {0,2,4,6}, base = (k4&4)?1:0
        int ch   = a_k4 >> 3;
        int base = (a_k4 & 4) ? 1 : 0;
        int kp   = ch * 8 + base;
#pragma unroll
        for (int i = 0; i < 4; i++) {
            int m = a_m + i * 32;
            As[m][kp + 0] = __uint_as_float(f2tf(ra[i].x));
            As[m][kp + 2] = __uint_as_float(f2tf(ra[i].y));
            As[m][kp + 4] = __uint_as_float(f2tf(ra[i].z));
            As[m][kp + 6] = __uint_as_float(f2tf(ra[i].w));
        }
        if (!TRANSB) {
#pragma unroll
            for (int i = 0; i < 4; i++) {
                int k = b_k + i * 8;
                int c = k & 7;
                int kpb = (k >> 3) * 8 + (c & 3) * 2 + (c >> 2);
                Bs[b_n4 + 0][kpb] = __uint_as_float(f2tf(rb[i].x));
                Bs[b_n4 + 1][kpb] = __uint_as_float(f2tf(rb[i].y));
                Bs[b_n4 + 2][kpb] = __uint_as_float(f2tf(rb[i].z));
                Bs[b_n4 + 3][kpb] = __uint_as_float(f2tf(rb[i].w));
            }
        } else {
            int ch2   = a_k4 >> 3;
            int base2 = (a_k4 & 4) ? 1 : 0;
            int kp2   = ch2 * 8 + base2;
#pragma unroll
            for (int i = 0; i < 4; i++) {
                int n = a_m + i * 32;
                Bs[n][kp2 + 0] = __uint_as_float(f2tf(rb[i].x));
                Bs[n][kp2 + 2] = __uint_as_float(f2tf(rb[i].y));
                Bs[n][kp2 + 4] = __uint_as_float(f2tf(rb[i].z));
                Bs[n][kp2 + 6] = __uint_as_float(f2tf(rb[i].w));
            }
        }
    };

    load_tiles(0);

    for (int k0 = 0; k0 < K; k0 += 32) {
        store_tiles();
        __syncthreads();
        if (k0 + 32 < K) load_tiles(k0 + 32);

#pragma unroll
        for (int chk = 0; chk < 4; chk++) {
            int kb = chk * 8 + tig * 2;
            unsigned af[4][4];
#pragma unroll
            for (int mt = 0; mt < 4; mt++) {
                int r = mbase + mt * 16 + gid;
                float2 p0 = *(const float2*)&As[r][kb];
                float2 p1 = *(const float2*)&As[r + 8][kb];
                af[mt][0] = __float_as_uint(p0.x);
                af[mt][1] = __float_as_uint(p1.x);
                af[mt][2] = __float_as_uint(p0.y);
                af[mt][3] = __float_as_uint(p1.y);
            }
            unsigned bf[4][2];
#pragma unroll
            for (int nt = 0; nt < 4; nt++) {
                int n = nbase + nt * 8 + gid;
                float2 q = *(const float2*)&Bs[n][kb];
                bf[nt][0] = __float_as_uint(q.x);
                bf[nt][1] = __float_as_uint(q.y);
            }
#pragma unroll
            for (int mt = 0; mt < 4; mt++)
#pragma unroll
                for (int nt = 0; nt < 4; nt++)
                    MMA8(acc[mt][nt], af[mt][0], af[mt][1], af[mt][2], af[mt][3],
                         bf[nt][0], bf[nt][1]);
        }
        __syncthreads();
    }

    // epilogue
#pragma unroll
    for (int mt = 0; mt < 4; mt++) {
#pragma unroll
        for (int nt = 0; nt < 4; nt++) {
            long long r  = row0 + mbase + mt * 16 + gid;
            long long cc = col0 + nbase + nt * 8 + tig * 2;
            float2 o0, o1;
            o0.x = acc[mt][nt][0] * alpha;
            o0.y = acc[mt][nt][1] * alpha;
            o1.x = acc[mt][nt][2] * alpha;
            o1.y = acc[mt][nt][3] * alpha;
            if (R) {
                float2 r0 = *(const float2*)&R[r * ldc + cc];
                float2 r1 = *(const float2*)&R[(r + 8) * ldc + cc];
                o0.x += r0.x; o0.y += r0.y;
                o1.x += r1.x; o1.y += r1.y;
            }
            *(float2*)&C[r * ldc + cc]       = o0;
            *(float2*)&C[(r + 8) * ldc + cc] = o1;
        }
    }
}

// ------------------------------------------------------------------- launch
extern "C" void kernel_launch(void* const* d_in, const int* in_sizes, int n_in,
                              void* d_out, int out_size) {
    const float* X    = (const float*)d_in[0];
    const float* ln_w = (const float*)d_in[1];
    const float* ln_b = (const float*)d_in[2];
    const float* W_in = (const float*)d_in[3];
    const float* W_out= (const float*)d_in[4];
    float* out = (float*)d_out;

    float *Xn, *QKV, *CTX, *SC;
    cudaGetSymbolAddress((void**)&Xn,  g_Xn);
    cudaGetSymbolAddress((void**)&QKV, g_QKV);
    cudaGetSymbolAddress((void**)&CTX, g_ctx);
    cudaGetSymbolAddress((void**)&SC,  g_sc);

    // 1) layernorm
    ln_kernel<<<TT, 256>>>(X, ln_w, ln_b, Xn);

    // 2) QKV = Xn @ W_in   [8192,6144]
    gemm_tf32<false><<<dim3(6144 / 128, 8192 / 128, 1), 256>>>(
        Xn, W_in, QKV, nullptr,
        8192, 6144, 2048, 2048, 6144, 6144,
        0, 0, 0, 0, 0, 0, 1, 1.0f);

    // 3) RoPE (in place on Q and K)
    rope_kernel<<<(8192 * 16 * 32) / 256, 256>>>(QKV);

    // 4) scores(b,h) = (1/sqrt(128)) * Q @ K^T
    const float scale = 0.08838834764831845f;
    gemm_tf32<true><<<dim3(16, 16, 64), 256>>>(
        QKV, QKV + 2048, SC, nullptr,
        2048, 2048, 128, 6144, 6144, 2048,
        2048LL * 6144, 128,
        2048LL * 6144, 128,
        16LL * 2048 * 2048, 2048LL * 2048,
        16, scale);

    // 5) softmax rows (in place)
    softmax_kernel<<<64 * 2048, 256>>>(SC);

    // 6) ctx(b,h) = probs @ V
    gemm_tf32<false><<<dim3(1, 16, 64), 256>>>(
        SC, QKV + 4096, CTX, nullptr,
        2048, 128, 2048, 2048, 6144, 2048,
        16LL * 2048 * 2048, 2048LL * 2048,
        2048LL * 6144, 128,
        2048LL * 2048, 128,
        16, 1.0f);

    // 7) out = ctx @ W_out + X
    gemm_tf32<false><<<dim3(2048 / 128, 8192 / 128, 1), 256>>>(
        CTX, W_out, out, X,
        8192, 2048, 2048, 2048, 2048, 2048,
        0, 0, 0, 0, 0, 0, 1, 1.0f);
}

// round 3
// speedup vs baseline: 1.4737x; 1.0002x over previous
#include <cuda_runtime.h>
#include <math.h>

// Problem constants: B=4, S=2048, D=2048, H=16, Dh=128
#define TT 8192            // B*S tokens

// ---------------- scratch (static device arrays; no allocation allowed) ----
__device__ float g_Xn [8192ULL * 2048];          //  64 MB   layernorm output
__device__ float g_QKV[8192ULL * 6144];          // 192 MB   [token, 3D]  Q|K|V
__device__ float g_ctx[8192ULL * 2048];          //  64 MB   attention context
__device__ float g_sc [64ULL * 2048 * 2048];     //   1 GB   scores/probs per (b,h)

// ---------------------------------------------------------------- layernorm
__global__ void ln_kernel(const float* __restrict__ X,
                          const float* __restrict__ w,
                          const float* __restrict__ b,
                          float* __restrict__ Y) {
    const int D = 2048;
    const float* x = X + (size_t)blockIdx.x * D;
    float* y       = Y + (size_t)blockIdx.x * D;
    int tid = threadIdx.x;

    float v[8];
    float s = 0.f;
#pragma unroll
    for (int i = 0; i < 8; i++) { v[i] = x[tid + i * 256]; s += v[i]; }

    __shared__ float sh[8];
#pragma unroll
    for (int o = 16; o > 0; o >>= 1) s += __shfl_xor_sync(0xffffffffu, s, o);
    if ((tid & 31) == 0) sh[tid >> 5] = s;
    __syncthreads();
    float tot = 0.f;
#pragma unroll
    for (int i = 0; i < 8; i++) tot += sh[i];
    float mean = tot * (1.0f / 2048.0f);

    float sq = 0.f;
#pragma unroll
    for (int i = 0; i < 8; i++) { float d = v[i] - mean; sq += d * d; }
    __syncthreads();
#pragma unroll
    for (int o = 16; o > 0; o >>= 1) sq += __shfl_xor_sync(0xffffffffu, sq, o);
    if ((tid & 31) == 0) sh[tid >> 5] = sq;
    __syncthreads();
    float vtot = 0.f;
#pragma unroll
    for (int i = 0; i < 8; i++) vtot += sh[i];
    float rstd = rsqrtf(vtot * (1.0f / 2048.0f) + 1e-5f);

#pragma unroll
    for (int i = 0; i < 8; i++) {
        int c = tid + i * 256;
        y[c] = (v[i] - mean) * rstd * w[c] + b[c];
    }
}

// --------------------------------------------------------------------- rope
__global__ void rope_kernel(float* __restrict__ QKV) {
    int idx = blockIdx.x * blockDim.x + threadIdx.x;   // 8192*16*32 total
    if (idx >= 8192 * 16 * 32) return;
    int j = idx & 31;
    int h = (idx >> 5) & 15;
    int t = idx >> 9;
    int s = t & 2047;

    float inv = (float)exp(-(double)j * (9.210340371976184 / 32.0));
    float ang = (float)s * inv;
    float si = sinf(ang), c = cosf(ang);

    size_t base = (size_t)t * 6144 + (size_t)h * 128 + 2 * j;
    float* q = QKV + base;
    float* k = QKV + base + 2048;
    float q0 = q[0], q1 = q[1];
    q[0] = q0 * c - q1 * si;
    q[1] = q1 * c + q0 * si;
    float k0 = k[0], k1 = k[1];
    k[0] = k0 * c - k1 * si;
    k[1] = k1 * c + k0 * si;
}

// ------------------------------------------------------------------ softmax
__global__ void softmax_kernel(float* __restrict__ S) {
    const int N = 2048;
    float* row = S + (size_t)blockIdx.x * N;
    int tid = threadIdx.x;

    float v[8];
    float m = -1e30f;
#pragma unroll
    for (int i = 0; i < 8; i++) { v[i] = row[tid + i * 256]; m = fmaxf(m, v[i]); }

    __shared__ float sh[8];
#pragma unroll
    for (int o = 16; o > 0; o >>= 1) m = fmaxf(m, __shfl_xor_sync(0xffffffffu, m, o));
    if ((tid & 31) == 0) sh[tid >> 5] = m;
    __syncthreads();
    float rm = -1e30f;
#pragma unroll
    for (int i = 0; i < 8; i++) rm = fmaxf(rm, sh[i]);

    float s = 0.f;
#pragma unroll
    for (int i = 0; i < 8; i++) { v[i] = __expf(v[i] - rm); s += v[i]; }
    __syncthreads();
#pragma unroll
    for (int o = 16; o > 0; o >>= 1) s += __shfl_xor_sync(0xffffffffu, s, o);
    if ((tid & 31) == 0) sh[tid >> 5] = s;
    __syncthreads();
    float tot = 0.f;
#pragma unroll
    for (int i = 0; i < 8; i++) tot += sh[i];
    float inv = 1.0f / tot;

#pragma unroll
    for (int i = 0; i < 8; i++) row[tid + i * 256] = v[i] * inv;
}

// ---------------------------------------------------------------- tf32 gemm
__device__ __forceinline__ unsigned f2tf(float x) {
    unsigned u;
    asm("cvt.rna.tf32.f32 %0, %1;" : "=r"(u) : "f"(x));
    return u;
}

#define MMA8(c, a0, a1, a2, a3, b0, b1)                                      \
    asm volatile(                                                            \
        "mma.sync.aligned.m16n8k8.row.col.f32.tf32.tf32.f32 "                \
        "{%0,%1,%2,%3}, {%4,%5,%6,%7}, {%8,%9}, {%0,%1,%2,%3};"              \
        : "+f"(c[0]), "+f"(c[1]), "+f"(c[2]), "+f"(c[3])                     \
        : "r"(a0), "r"(a1), "r"(a2), "r"(a3), "r"(b0), "r"(b1))

// C[M,N] = alpha * A[M,K] @ op(B) (+Res), batched over z = b*Hs + h.
// TRANSB=false: B is [K,N]; TRANSB=true: B is [N,K] (C = A B^T).
// Block tile 128x128x32, 256 threads (8 warps 2x4), warp tile 64x32.
// Smem inner-k within each 8-chunk permuted (0,4,1,5,2,6,3,7) so that the
// (c, c+4) fragment pair is one LDS.64.
template <bool TRANSB>
__global__ void __launch_bounds__(256)
gemm_tf32(const float* __restrict__ A, const float* __restrict__ B,
          float* __restrict__ C, const float* __restrict__ Res,
          int M, int N, int K, int lda, int ldb, int ldc,
          long long aB, long long aH, long long bB, long long bH,
          long long cB, long long cH, int Hs, float alpha) {
    int z = blockIdx.z;
    int bb = z / Hs, hh = z % Hs;
    A += bb * aB + hh * aH;
    B += bb * bB + hh * bH;
    C += bb * cB + hh * cH;
    const float* R = Res ? Res + bb * cB + hh * cH : nullptr;

    __shared__ float As[128][36];
    __shared__ float Bs[128][36];

    const int tid  = threadIdx.x;
    const int row0 = blockIdx.y * 128;
    const int col0 = blockIdx.x * 128;
    const int warp = tid >> 5, lane = tid & 31;
    const int wm = warp & 1, wn = warp >> 1;      // 2 x 4 warps
    const int mbase = wm * 64, nbase = wn * 32;   // warp tile 64x32
    const int gid = lane >> 2, tig = lane & 3;

    float acc[4][4][4];
#pragma unroll
    for (int i = 0; i < 4; i++)
#pragma unroll
        for (int j = 0; j < 4; j++)
#pragma unroll
            for (int l = 0; l < 4; l++) acc[i][j][l] = 0.f;

    // per-thread gmem tile coords
    // A: idx = tid + i*256 -> m = idx>>3, k4 = (idx&7)*4
    const int a_m  = tid >> 3;            // rows stride 32 per i (256/8)
    const int a_k4 = (tid & 7) << 2;
    // B (!TRANSB): k = idx>>5, n4 = (idx&31)*4
    const int b_k  = tid >> 5;            // +8 per i
    const int b_n4 = (tid & 31) << 2;

    float4 ra[4], rb[4];

    auto load_tiles = [&](int k0) {
#pragma unroll
        for (int i = 0; i < 4; i++) {
            int m = a_m + i * 32;
            ra[i] = *(const float4*)&A[(long long)(row0 + m) * lda + k0 + a_k4];
        }
        if (!TRANSB) {
#pragma unroll
            for (int i = 0; i < 4; i++) {
                int k = b_k + i * 8;
                rb[i] = *(const float4*)&B[(long long)(k0 + k) * ldb + col0 + b_n4];
            }
        } else {
#pragma unroll
            for (int i = 0; i < 4; i++) {
                int n = a_m + i * 32;
                rb[i] = *(const float4*)&B[(long long)(col0 + n) * ldb + k0 + a_k4];
            }
        }
    };

    auto store_tiles = [&]() {
        // A: k4..k4+3 map to chunk*8 + base + {0,2,4,6}, base = (k4&4)?1:0
        int ch   = a_k4 >> 3;
        int base = (a_k4 & 4) ? 1 : 0;
        int kp   = ch * 8 + base;
#pragma unroll
        for (int i = 0; i < 4; i++) {
            int m = a_m + i * 32;
            As[m][kp + 0] = __uint_as_float(f2tf(ra[i].x));
            As[m][kp + 2] = __uint_as_float(f2tf(ra[i].y));
            As[m][kp + 4] = __uint_as_float(f2tf(ra[i].z));
            As[m][kp + 6] = __uint_as_float(f2tf(ra[i].w));
        }
        if (!TRANSB) {
#pragma unroll
            for (int i = 0; i < 4; i++) {
                int k = b_k + i * 8;
                int c = k & 7;
                int kpb = (k >> 3) * 8 + (c & 3) * 2 + (c >> 2);
                Bs[b_n4 + 0][kpb] = __uint_as_float(f2tf(rb[i].x));
                Bs[b_n4 + 1][kpb] = __uint_as_float(f2tf(rb[i].y));
                Bs[b_n4 + 2][kpb] = __uint_as_float(f2tf(rb[i].z));
                Bs[b_n4 + 3][kpb] = __uint_as_float(f2tf(rb[i].w));
            }
        } else {
            int ch2   = a_k4 >> 3;
            int base2 = (a_k4 & 4) ? 1 : 0;
            int kp2   = ch2 * 8 + base2;
#pragma unroll
            for (int i = 0; i < 4; i++) {
                int n = a_m + i * 32;
                Bs[n][kp2 + 0] = __uint_as_float(f2tf(rb[i].x));
                Bs[n][kp2 + 2] = __uint_as_float(f2tf(rb[i].y));
                Bs[n][kp2 + 4] = __uint_as_float(f2tf(rb[i].z));
                Bs[n][kp2 + 6] = __uint_as_float(f2tf(rb[i].w));
            }
        }
    };

    load_tiles(0);

    for (int k0 = 0; k0 < K; k0 += 32) {
        store_tiles();
        __syncthreads();
        if (k0 + 32 < K) load_tiles(k0 + 32);

#pragma unroll
        for (int chk = 0; chk < 4; chk++) {
            int kb = chk * 8 + tig * 2;
            unsigned af[4][4];
#pragma unroll
            for (int mt = 0; mt < 4; mt++) {
                int r = mbase + mt * 16 + gid;
                float2 p0 = *(const float2*)&As[r][kb];
                float2 p1 = *(const float2*)&As[r + 8][kb];
                af[mt][0] = __float_as_uint(p0.x);
                af[mt][1] = __float_as_uint(p1.x);
                af[mt][2] = __float_as_uint(p0.y);
                af[mt][3] = __float_as_uint(p1.y);
            }
            unsigned bf[4][2];
#pragma unroll
            for (int nt = 0; nt < 4; nt++) {
                int n = nbase + nt * 8 + gid;
                float2 q = *(const float2*)&Bs[n][kb];
                bf[nt][0] = __float_as_uint(q.x);
                bf[nt][1] = __float_as_uint(q.y);
            }
#pragma unroll
            for (int mt = 0; mt < 4; mt++)
#pragma unroll
                for (int nt = 0; nt < 4; nt++)
                    MMA8(acc[mt][nt], af[mt][0], af[mt][1], af[mt][2], af[mt][3],
                         bf[nt][0], bf[nt][1]);
        }
        __syncthreads();
    }

    // epilogue
#pragma unroll
    for (int mt = 0; mt < 4; mt++) {
#pragma unroll
        for (int nt = 0; nt < 4; nt++) {
            long long r  = row0 + mbase + mt * 16 + gid;
            long long cc = col0 + nbase + nt * 8 + tig * 2;
            float2 o0, o1;
            o0.x = acc[mt][nt][0] * alpha;
            o0.y = acc[mt][nt][1] * alpha;
            o1.x = acc[mt][nt][2] * alpha;
            o1.y = acc[mt][nt][3] * alpha;
            if (R) {
                float2 r0 = *(const float2*)&R[r * ldc + cc];
                float2 r1 = *(const float2*)&R[(r + 8) * ldc + cc];
                o0.x += r0.x; o0.y += r0.y;
                o1.x += r1.x; o1.y += r1.y;
            }
            *(float2*)&C[r * ldc + cc]       = o0;
            *(float2*)&C[(r + 8) * ldc + cc] = o1;
        }
    }
}

// ------------------------------------------------------------------- launch
extern "C" void kernel_launch(void* const* d_in, const int* in_sizes, int n_in,
                              void* d_out, int out_size) {
    const float* X    = (const float*)d_in[0];
    const float* ln_w = (const float*)d_in[1];
    const float* ln_b = (const float*)d_in[2];
    const float* W_in = (const float*)d_in[3];
    const float* W_out= (const float*)d_in[4];
    float* out = (float*)d_out;

    float *Xn, *QKV, *CTX, *SC;
    cudaGetSymbolAddress((void**)&Xn,  g_Xn);
    cudaGetSymbolAddress((void**)&QKV, g_QKV);
    cudaGetSymbolAddress((void**)&CTX, g_ctx);
    cudaGetSymbolAddress((void**)&SC,  g_sc);

    // 1) layernorm
    ln_kernel<<<TT, 256>>>(X, ln_w, ln_b, Xn);

    // 2) QKV = Xn @ W_in   [8192,6144]
    gemm_tf32<false><<<dim3(6144 / 128, 8192 / 128, 1), 256>>>(
        Xn, W_in, QKV, nullptr,
        8192, 6144, 2048, 2048, 6144, 6144,
        0, 0, 0, 0, 0, 0, 1, 1.0f);

    // 3) RoPE (in place on Q and K)
    rope_kernel<<<(8192 * 16 * 32) / 256, 256>>>(QKV);

    // 4) scores(b,h) = (1/sqrt(128)) * Q @ K^T
    const float scale = 0.08838834764831845f;
    gemm_tf32<true><<<dim3(16, 16, 64), 256>>>(
        QKV, QKV + 2048, SC, nullptr,
        2048, 2048, 128, 6144, 6144, 2048,
        2048LL * 6144, 128,
        2048LL * 6144, 128,
        16LL * 2048 * 2048, 2048LL * 2048,
        16, scale);

    // 5) softmax rows (in place)
    softmax_kernel<<<64 * 2048, 256>>>(SC);

    // 6) ctx(b,h) = probs @ V
    gemm_tf32<false><<<dim3(1, 16, 64), 256>>>(
        SC, QKV + 4096, CTX, nullptr,
        2048, 128, 2048, 2048, 6144, 2048,
        16LL * 2048 * 2048, 2048LL * 2048,
        2048LL * 6144, 128,
        2048LL * 2048, 128,
        16, 1.0f);

    // 7) out = ctx @ W_out + X
    gemm_tf32<false><<<dim3(2048 / 128, 8192 / 128, 1), 256>>>(
        CTX, W_out, out, X,
        8192, 2048, 2048, 2048, 2048, 2048,
        0, 0, 0, 0, 0, 0, 1, 1.0f);
}

// round 4
// speedup vs baseline: 6.6854x; 4.5365x over previous
#include <cuda_runtime.h>
#include <cuda_bf16.h>
#include <math.h>

typedef __nv_bfloat16 bf16;

// Problem: B=4, S=2048, D=2048, H=16, Dh=128
#define TT 8192

// ---------------- scratch (static device arrays) ---------------------------
__device__ bf16 g_Xn [8192ULL * 2048];           // LN output (bf16)
__device__ bf16 g_WiT[6144ULL * 2048];           // W_in^T  bf16 [n][k]
__device__ bf16 g_WoT[2048ULL * 2048];           // W_out^T bf16 [n][k]
__device__ bf16 g_Q  [64ULL * 2048 * 128];       // [b*h][s][d] roped
__device__ bf16 g_K  [64ULL * 2048 * 128];
__device__ bf16 g_Vb [64ULL * 2048 * 128];       // [b*h][s][d]
__device__ bf16 g_Vt [64ULL * 128 * 2048];       // [b*h][d][s]
__device__ bf16 g_ctx[8192ULL * 2048];           // attention out (bf16)
__device__ float g_invfreq[32];

// ---------------------------------------------------------------- helpers
__device__ __forceinline__ unsigned pk(float lo, float hi) {
    unsigned r;
    asm("cvt.rn.bf16x2.f32 %0, %1, %2;" : "=r"(r) : "f"(hi), "f"(lo));
    return r;
}
__device__ __forceinline__ void cpa16(unsigned s, const void* g) {
    asm volatile("cp.async.cg.shared.global [%0], [%1], 16;" :: "r"(s), "l"(g));
}
#define CP_COMMIT asm volatile("cp.async.commit_group;")
#define CP_WAIT(n) asm volatile("cp.async.wait_group %0;" :: "n"(n))

#define MMA_BF16(d, a0, a1, a2, a3, b0, b1)                                   \
    asm volatile(                                                             \
        "mma.sync.aligned.m16n8k16.row.col.f32.bf16.bf16.f32 "                \
        "{%0,%1,%2,%3}, {%4,%5,%6,%7}, {%8,%9}, {%0,%1,%2,%3};"               \
        : "+f"(d[0]), "+f"(d[1]), "+f"(d[2]), "+f"(d[3])                      \
        : "r"(a0), "r"(a1), "r"(a2), "r"(a3), "r"(b0), "r"(b1))

// ---------------------------------------------------------------- init
__global__ void init_invfreq() {
    int j = threadIdx.x;
    if (j < 32) g_invfreq[j] = (float)exp(-(double)j * (9.210340371976184 / 32.0));
}

// ------------------------------------------------------- weight conv+transpose
// W[K][N] fp32 -> Wt[N][K] bf16
__global__ void wconv(const float* __restrict__ W, bf16* __restrict__ Wt,
                      int K, int N) {
    __shared__ float t[32][33];
    int n0 = blockIdx.x * 32, k0 = blockIdx.y * 32;
    int tx = threadIdx.x & 31, ty = threadIdx.x >> 5;
#pragma unroll
    for (int i = 0; i < 4; i++)
        t[ty + i * 8][tx] = W[(size_t)(k0 + ty + i * 8) * N + n0 + tx];
    __syncthreads();
#pragma unroll
    for (int i = 0; i < 4; i++)
        Wt[(size_t)(n0 + ty + i * 8) * K + k0 + tx] =
            __float2bfloat16_rn(t[tx][ty + i * 8]);
}

// --------------------------------------------------------------- V transpose
// Vb[bh][s][d] -> Vt[bh][d][s]
__global__ void transpose_v(const bf16* __restrict__ Vb, bf16* __restrict__ Vt) {
    __shared__ bf16 t[32][33];
    int s0 = blockIdx.x * 32, d0 = blockIdx.y * 32, bh = blockIdx.z;
    int tx = threadIdx.x & 31, ty = threadIdx.x >> 5;
    const bf16* in = Vb + (size_t)bh * 2048 * 128;
    bf16* out = Vt + (size_t)bh * 128 * 2048;
#pragma unroll
    for (int i = 0; i < 4; i++)
        t[ty + i * 8][tx] = in[(size_t)(s0 + ty + i * 8) * 128 + d0 + tx];
    __syncthreads();
#pragma unroll
    for (int i = 0; i < 4; i++)
        out[(size_t)(d0 + ty + i * 8) * 2048 + s0 + tx] = t[tx][ty + i * 8];
}

// ---------------------------------------------------------------- layernorm
__global__ void ln_kernel(const float* __restrict__ X,
                          const float* __restrict__ w,
                          const float* __restrict__ b,
                          bf16* __restrict__ Y) {
    const int D = 2048;
    const float* x = X + (size_t)blockIdx.x * D;
    bf16* y = Y + (size_t)blockIdx.x * D;
    int tid = threadIdx.x;

    float v[8];
    float s = 0.f;
#pragma unroll
    for (int i = 0; i < 8; i++) { v[i] = x[tid + i * 256]; s += v[i]; }

    __shared__ float sh[8];
#pragma unroll
    for (int o = 16; o > 0; o >>= 1) s += __shfl_xor_sync(0xffffffffu, s, o);
    if ((tid & 31) == 0) sh[tid >> 5] = s;
    __syncthreads();
    float tot = 0.f;
#pragma unroll
    for (int i = 0; i < 8; i++) tot += sh[i];
    float mean = tot * (1.0f / 2048.0f);

    float sq = 0.f;
#pragma unroll
    for (int i = 0; i < 8; i++) { float d = v[i] - mean; sq += d * d; }
    __syncthreads();
#pragma unroll
    for (int o = 16; o > 0; o >>= 1) sq += __shfl_xor_sync(0xffffffffu, sq, o);
    if ((tid & 31) == 0) sh[tid >> 5] = sq;
    __syncthreads();
    float vtot = 0.f;
#pragma unroll
    for (int i = 0; i < 8; i++) vtot += sh[i];
    float rstd = rsqrtf(vtot * (1.0f / 2048.0f) + 1e-5f);

#pragma unroll
    for (int i = 0; i < 8; i++) {
        int c = tid + i * 256;
        y[c] = __float2bfloat16_rn((v[i] - mean) * rstd * w[c] + b[c]);
    }
}

// ------------------------------------------------------------------- GEMM
// C[M,N] = A[M,K] @ B^T where A bf16 [M][K], B bf16 [N][K].
// EPI==0: write fp32 C (+ optional fp32 residual Res).
// EPI==1: QKV epilogue — rope on Q,K (d<64 pairs), scatter to Qo/Ko/Vo
//         bf16 [b*16+h][s][d].
// Block tile 128x128x32, 256 thr (8 warps 2x4), warp tile 64x32, cp.async x2.
template <int EPI>
__global__ void __launch_bounds__(256, 2)
gemm_bf16(const bf16* __restrict__ A, const bf16* __restrict__ Bm,
          float* __restrict__ C, const float* __restrict__ Res,
          bf16* __restrict__ Qo, bf16* __restrict__ Ko, bf16* __restrict__ Vo,
          int N, int K) {
    __shared__ unsigned As[2][128 * 20];   // 128 rows x 32 bf16, pad to 40
    __shared__ unsigned Bs[2][128 * 20];

    const int tid = threadIdx.x;
    const int row0 = blockIdx.y * 128;
    const int col0 = blockIdx.x * 128;
    const int warp = tid >> 5, lane = tid & 31;
    const int gid = lane >> 2, tig = lane & 3;
    const int mbase = (warp & 1) * 64, nbase = (warp >> 1) * 32;

    const int cr = tid >> 2, cc = tid & 3;   // copy: row, 16B-chunk
    unsigned sa0 = (unsigned)__cvta_generic_to_shared(&As[0][0]);
    unsigned sb0 = (unsigned)__cvta_generic_to_shared(&Bs[0][0]);

    auto copy_tile = [&](int kt, int buf) {
        const bf16* ap = A + (size_t)(row0 + cr) * K + kt * 32 + cc * 8;
        const bf16* bp = Bm + (size_t)(col0 + cr) * K + kt * 32 + cc * 8;
        unsigned da = sa0 + buf * (128 * 20 * 4) + cr * 80 + cc * 16;
        unsigned db = sb0 + buf * (128 * 20 * 4) + cr * 80 + cc * 16;
        cpa16(da, ap);
        cpa16(da + 64 * 80, ap + (size_t)64 * K);
        cpa16(db, bp);
        cpa16(db + 64 * 80, bp + (size_t)64 * K);
    };

    float acc[4][4][4];
#pragma unroll
    for (int i = 0; i < 4; i++)
#pragma unroll
        for (int j = 0; j < 4; j++)
#pragma unroll
            for (int l = 0; l < 4; l++) acc[i][j][l] = 0.f;

    const int nkt = K / 32;
    copy_tile(0, 0); CP_COMMIT;
    copy_tile(1, 1); CP_COMMIT;

    for (int kt = 0; kt < nkt; kt++) {
        if (kt + 1 < nkt) { CP_WAIT(1); } else { CP_WAIT(0); }
        __syncthreads();
        const unsigned* Au = As[kt & 1];
        const unsigned* Bu = Bs[kt & 1];
#pragma unroll
        for (int kc = 0; kc < 2; kc++) {
            unsigned af[4][4], bfb[4][2];
#pragma unroll
            for (int mt = 0; mt < 4; mt++) {
                int ra = (mbase + mt * 16 + gid) * 20 + tig + 8 * kc;
                af[mt][0] = Au[ra];
                af[mt][1] = Au[ra + 8 * 20];
                af[mt][2] = Au[ra + 4];
                af[mt][3] = Au[ra + 8 * 20 + 4];
            }
#pragma unroll
            for (int nt = 0; nt < 4; nt++) {
                int rb = (nbase + nt * 8 + gid) * 20 + tig + 8 * kc;
                bfb[nt][0] = Bu[rb];
                bfb[nt][1] = Bu[rb + 4];
            }
#pragma unroll
            for (int mt = 0; mt < 4; mt++)
#pragma unroll
                for (int nt = 0; nt < 4; nt++)
                    MMA_BF16(acc[mt][nt], af[mt][0], af[mt][1], af[mt][2],
                             af[mt][3], bfb[nt][0], bfb[nt][1]);
        }
        __syncthreads();
        if (kt + 2 < nkt) { copy_tile(kt + 2, kt & 1); CP_COMMIT; }
    }

    if (EPI == 0) {
#pragma unroll
        for (int mt = 0; mt < 4; mt++) {
#pragma unroll
            for (int nt = 0; nt < 4; nt++) {
                size_t r = row0 + mbase + mt * 16 + gid;
                int c = col0 + nbase + nt * 8 + tig * 2;
                float2 o0 = {acc[mt][nt][0], acc[mt][nt][1]};
                float2 o1 = {acc[mt][nt][2], acc[mt][nt][3]};
                if (Res) {
                    float2 r0 = *(const float2*)&Res[r * N + c];
                    float2 r1 = *(const float2*)&Res[(r + 8) * N + c];
                    o0.x += r0.x; o0.y += r0.y;
                    o1.x += r1.x; o1.y += r1.y;
                }
                *(float2*)&C[r * N + c] = o0;
                *(float2*)&C[(r + 8) * N + c] = o1;
            }
        }
    } else {
        int qkv = col0 >> 11;
        int h = (col0 >> 7) & 15;
        bf16* dst = (qkv == 0) ? Qo : (qkv == 1) ? Ko : Vo;
        bool isv = (qkv == 2);
#pragma unroll
        for (int nt = 0; nt < 4; nt++) {
            int d = nbase + nt * 8 + tig * 2;
            bool dorope = (!isv) && (d < 64);
            float inv = dorope ? g_invfreq[d >> 1] : 0.f;
#pragma unroll
            for (int mt = 0; mt < 4; mt++) {
                int r0 = row0 + mbase + mt * 16 + gid;
                int b = r0 >> 11, s0 = r0 & 2047;
                float v0 = acc[mt][nt][0], v1 = acc[mt][nt][1];
                float v2 = acc[mt][nt][2], v3 = acc[mt][nt][3];
                if (dorope) {
                    float a0 = (float)s0 * inv, a1 = (float)(s0 + 8) * inv;
                    float c0 = cosf(a0), sn0 = sinf(a0);
                    float c1 = cosf(a1), sn1 = sinf(a1);
                    float t0 = v0 * c0 - v1 * sn0;
                    v1 = v1 * c0 + v0 * sn0; v0 = t0;
                    float t2 = v2 * c1 - v3 * sn1;
                    v3 = v3 * c1 + v2 * sn1; v2 = t2;
                }
                size_t base = ((size_t)(b * 16 + h) * 2048 + s0) * 128 + d;
                *(unsigned*)&dst[base] = pk(v0, v1);
                *(unsigned*)&dst[base + 8 * 128] = pk(v2, v3);
            }
        }
    }
}

// ----------------------------------------------------------- flash attention
// grid (16 qtiles, 64 bh), 256 thr. Br=Bc=128, Dh=128.
// smem: Q | K[2] | Vt[2], each 128x128 bf16, 16B-chunk XOR swizzle.
__global__ void __launch_bounds__(256)
flash_kernel(const bf16* __restrict__ Qg, const bf16* __restrict__ Kg,
             const bf16* __restrict__ Vtg, bf16* __restrict__ ctx) {
    extern __shared__ bf16 sm[];
    unsigned* SU = (unsigned*)sm;
    const int QW = 0, KW0 = 8192, KW1 = 16384, VW0 = 24576, VW1 = 32768;

    const int tid = threadIdx.x, wid = tid >> 5, lane = tid & 31;
    const int gid = lane >> 2, tig = lane & 3;
    const int qt = blockIdx.x, bh = blockIdx.y;
    const int q0 = qt * 128;
    const size_t kbase = (size_t)bh * 2048 * 128;
    const size_t vbase = (size_t)bh * 128 * 2048;

    unsigned sbase = (unsigned)__cvta_generic_to_shared(sm);

    auto ldtile = [&](int wofs, const bf16* gsrc, size_t rowstride) {
#pragma unroll
        for (int i = 0; i < 8; i++) {
            int id = tid + i * 256;
            int r = id >> 4, c = id & 15;
            unsigned saddr = sbase + (unsigned)(wofs + r * 64 + ((c ^ (r & 7)) << 2)) * 4;
            cpa16(saddr, gsrc + (size_t)r * rowstride + c * 8);
        }
    };

    ldtile(QW, Qg + kbase + (size_t)q0 * 128, 128); CP_COMMIT;
    ldtile(KW0, Kg + kbase, 128);
    ldtile(VW0, Vtg + vbase, 2048); CP_COMMIT;
    ldtile(KW1, Kg + kbase + 128 * 128, 128);
    ldtile(VW1, Vtg + vbase + 128, 2048); CP_COMMIT;

    CP_WAIT(2);
    __syncthreads();

    const int r0 = wid * 16 + gid, r1 = r0 + 8;
    unsigned qf[8][4];
#pragma unroll
    for (int kc = 0; kc < 8; kc++) {
        qf[kc][0] = SU[QW + r0 * 64 + (((2 * kc) ^ (r0 & 7)) << 2) + tig];
        qf[kc][1] = SU[QW + r1 * 64 + (((2 * kc) ^ (r1 & 7)) << 2) + tig];
        qf[kc][2] = SU[QW + r0 * 64 + (((2 * kc + 1) ^ (r0 & 7)) << 2) + tig];
        qf[kc][3] = SU[QW + r1 * 64 + (((2 * kc + 1) ^ (r1 & 7)) << 2) + tig];
    }

    float o[16][4];
#pragma unroll
    for (int i = 0; i < 16; i++)
#pragma unroll
        for (int j = 0; j < 4; j++) o[i][j] = 0.f;
    float m0 = -1e30f, m1 = -1e30f, l0 = 0.f, l1 = 0.f;
    const float scale = 0.08838834764831845f;

    for (int t = 0; t < 16; t++) {
        if (t < 15) { CP_WAIT(1); } else { CP_WAIT(0); }
        __syncthreads();
        const int KW = (t & 1) ? KW1 : KW0;
        const int VW = (t & 1) ? VW1 : VW0;

        float s[16][4];
#pragma unroll
        for (int nt = 0; nt < 16; nt++) {
#pragma unroll
            for (int i = 0; i < 4; i++) s[nt][i] = 0.f;
            int sr = nt * 8 + gid, sw = sr & 7;
#pragma unroll
            for (int kc = 0; kc < 8; kc++) {
                unsigned b0 = SU[KW + sr * 64 + (((2 * kc) ^ sw) << 2) + tig];
                unsigned b1 = SU[KW + sr * 64 + (((2 * kc + 1) ^ sw) << 2) + tig];
                MMA_BF16(s[nt], qf[kc][0], qf[kc][1], qf[kc][2], qf[kc][3], b0, b1);
            }
        }

        // scale + online softmax
        float mx0 = -1e30f, mx1 = -1e30f;
#pragma unroll
        for (int nt = 0; nt < 16; nt++) {
            s[nt][0] *= scale; s[nt][1] *= scale;
            s[nt][2] *= scale; s[nt][3] *= scale;
            mx0 = fmaxf(mx0, fmaxf(s[nt][0], s[nt][1]));
            mx1 = fmaxf(mx1, fmaxf(s[nt][2], s[nt][3]));
        }
        mx0 = fmaxf(mx0, __shfl_xor_sync(0xffffffffu, mx0, 1));
        mx0 = fmaxf(mx0, __shfl_xor_sync(0xffffffffu, mx0, 2));
        mx1 = fmaxf(mx1, __shfl_xor_sync(0xffffffffu, mx1, 1));
        mx1 = fmaxf(mx1, __shfl_xor_sync(0xffffffffu, mx1, 2));
        float mn0 = fmaxf(m0, mx0), mn1 = fmaxf(m1, mx1);
        float cor0 = __expf(m0 - mn0), cor1 = __expf(m1 - mn1);
        m0 = mn0; m1 = mn1;

        float sum0 = 0.f, sum1 = 0.f;
#pragma unroll
        for (int nt = 0; nt < 16; nt++) {
            s[nt][0] = __expf(s[nt][0] - mn0);
            s[nt][1] = __expf(s[nt][1] - mn0);
            s[nt][2] = __expf(s[nt][2] - mn1);
            s[nt][3] = __expf(s[nt][3] - mn1);
            sum0 += s[nt][0] + s[nt][1];
            sum1 += s[nt][2] + s[nt][3];
        }
        sum0 += __shfl_xor_sync(0xffffffffu, sum0, 1);
        sum0 += __shfl_xor_sync(0xffffffffu, sum0, 2);
        sum1 += __shfl_xor_sync(0xffffffffu, sum1, 1);
        sum1 += __shfl_xor_sync(0xffffffffu, sum1, 2);
        l0 = l0 * cor0 + sum0;
        l1 = l1 * cor1 + sum1;

#pragma unroll
        for (int dt = 0; dt < 16; dt++) {
            o[dt][0] *= cor0; o[dt][1] *= cor0;
            o[dt][2] *= cor1; o[dt][3] *= cor1;
        }

        unsigned pf[8][4];
#pragma unroll
        for (int kc2 = 0; kc2 < 8; kc2++) {
            pf[kc2][0] = pk(s[2 * kc2][0], s[2 * kc2][1]);
            pf[kc2][1] = pk(s[2 * kc2][2], s[2 * kc2][3]);
            pf[kc2][2] = pk(s[2 * kc2 + 1][0], s[2 * kc2 + 1][1]);
            pf[kc2][3] = pk(s[2 * kc2 + 1][2], s[2 * kc2 + 1][3]);
        }

#pragma unroll
        for (int dt = 0; dt < 16; dt++) {
            int vr = dt * 8 + gid, vw = vr & 7;
#pragma unroll
            for (int kc2 = 0; kc2 < 8; kc2++) {
                unsigned b0 = SU[VW + vr * 64 + (((2 * kc2) ^ vw) << 2) + tig];
                unsigned b1 = SU[VW + vr * 64 + (((2 * kc2 + 1) ^ vw) << 2) + tig];
                MMA_BF16(o[dt], pf[kc2][0], pf[kc2][1], pf[kc2][2], pf[kc2][3], b0, b1);
            }
        }

        __syncthreads();
        if (t + 2 < 16) {
            int buf = t & 1;
            ldtile(buf ? KW1 : KW0, Kg + kbase + (size_t)(t + 2) * 128 * 128, 128);
            ldtile(buf ? VW1 : VW0, Vtg + vbase + (size_t)(t + 2) * 128, 2048);
            CP_COMMIT;
        }
    }

    float rl0 = 1.0f / l0, rl1 = 1.0f / l1;
    int b = bh >> 4, h = bh & 15;
    size_t tok0 = (size_t)b * 2048 + q0 + r0;
    int colb = h * 128;
#pragma unroll
    for (int dt = 0; dt < 16; dt++) {
        int c = colb + dt * 8 + tig * 2;
        *(unsigned*)&ctx[tok0 * 2048 + c] = pk(o[dt][0] * rl0, o[dt][1] * rl0);
        *(unsigned*)&ctx[(tok0 + 8) * 2048 + c] = pk(o[dt][2] * rl1, o[dt][3] * rl1);
    }
}

// ------------------------------------------------------------------- launch
extern "C" void kernel_launch(void* const* d_in, const int* in_sizes, int n_in,
                              void* d_out, int out_size) {
    const float* X    = (const float*)d_in[0];
    const float* ln_w = (const float*)d_in[1];
    const float* ln_b = (const float*)d_in[2];
    const float* W_in = (const float*)d_in[3];
    const float* W_out= (const float*)d_in[4];
    float* out = (float*)d_out;

    bf16 *Xn, *WiT, *WoT, *Q, *K, *Vb, *Vt, *CTX;
    cudaGetSymbolAddress((void**)&Xn,  g_Xn);
    cudaGetSymbolAddress((void**)&WiT, g_WiT);
    cudaGetSymbolAddress((void**)&WoT, g_WoT);
    cudaGetSymbolAddress((void**)&Q,   g_Q);
    cudaGetSymbolAddress((void**)&K,   g_K);
    cudaGetSymbolAddress((void**)&Vb,  g_Vb);
    cudaGetSymbolAddress((void**)&Vt,  g_Vt);
    cudaGetSymbolAddress((void**)&CTX, g_ctx);

    cudaFuncSetAttribute(flash_kernel,
                         cudaFuncAttributeMaxDynamicSharedMemorySize, 163840);

    init_invfreq<<<1, 32>>>();
    wconv<<<dim3(192, 64), 256>>>(W_in, WiT, 2048, 6144);
    wconv<<<dim3(64, 64), 256>>>(W_out, WoT, 2048, 2048);
    ln_kernel<<<TT, 256>>>(X, ln_w, ln_b, Xn);

    // QKV + rope + scatter
    gemm_bf16<1><<<dim3(48, 64), 256>>>(Xn, WiT, nullptr, nullptr,
                                        Q, K, Vb, 6144, 2048);
    transpose_v<<<dim3(64, 4, 64), 256>>>(Vb, Vt);

    flash_kernel<<<dim3(16, 64), 256, 163840>>>(Q, K, Vt, CTX);

    // out = ctx @ W_out + X
    gemm_bf16<0><<<dim3(16, 64), 256>>>(CTX, WoT, out, X,
                                        nullptr, nullptr, nullptr, 2048, 2048);
}